// round 10
// baseline (speedup 1.0000x reference)
#include <cuda_runtime.h>
#include <cstdint>

#define NN 50000
#define EE 800000
#define DD 96
#define FF 128

// ---------------- scratch ----------------
__device__ __align__(16) float g_hA[NN * DD];
__device__ __align__(16) float g_hB[NN * DD];
__device__ __align__(16) float g_T[NN * 3 * DD];   // [N][288]: root | rel0 | rel1
__device__ __align__(16) float g_WfT[FF * DD];
__device__ int g_deg[2 * NN];
__device__ int g_cur[2 * NN];
__device__ int g_rowptr[2 * NN + 1];
__device__ int g_col[EE];
__device__ int g_bpart[256];

// ---------------- prep: zero deg + transpose Wf ----------------
__global__ void k_prep(const float* __restrict__ Wf, float* __restrict__ WfT,
                       int* __restrict__ deg, int N2) {
    int i = blockIdx.x * blockDim.x + threadIdx.x;
    if (i < N2) deg[i] = 0;
    if (i < DD * FF) {
        int d = i >> 7, k = i & 127;
        WfT[k * DD + d] = Wf[i];
    }
}

// ---------------- CSR build ----------------
__global__ void k_hist(const int* __restrict__ ei, const float* __restrict__ attr,
                       int* __restrict__ deg, int E) {
    int e = (blockIdx.x * blockDim.x + threadIdx.x) * 2;
    if (e >= E) return;
    int2 d2 = *(const int2*)(ei + E + e);
    float4 a4 = *(const float4*)(attr + 2 * e);
    atomicAdd(&deg[2 * d2.x + (a4.y > a4.x ? 1 : 0)], 1);
    if (e + 1 < E)
        atomicAdd(&deg[2 * d2.y + (a4.w > a4.z ? 1 : 0)], 1);
}

// --- A) block partial sums ---
__global__ __launch_bounds__(1024) void k_scanA(const int* __restrict__ deg,
                                                int* __restrict__ bpart, int N2) {
    __shared__ int red[32];
    int t = threadIdx.x;
    int i = blockIdx.x * 1024 + t;
    int v = (i < N2) ? deg[i] : 0;
#pragma unroll
    for (int o = 16; o; o >>= 1) v += __shfl_down_sync(~0u, v, o);
    if ((t & 31) == 0) red[t >> 5] = v;
    __syncthreads();
    if (t < 32) {
        int s = red[t];
#pragma unroll
        for (int o = 16; o; o >>= 1) s += __shfl_down_sync(~0u, s, o);
        if (t == 0) bpart[blockIdx.x] = s;
    }
}

// --- C) in-block scan of partials + per-block exclusive scan + offset ---
__global__ __launch_bounds__(1024) void k_scanC(const int* __restrict__ deg,
                                                const int* __restrict__ bpart,
                                                int* __restrict__ rowptr,
                                                int* __restrict__ cur, int N2, int nb) {
    __shared__ int sm[1024];
    __shared__ int bp[128];
    int t = threadIdx.x;
    if (t < 128) bp[t] = (t < nb) ? __ldg(&bpart[t]) : 0;
    __syncthreads();
#pragma unroll
    for (int o = 1; o < 128; o <<= 1) {
        int u = 0;
        if (t < 128 && t >= o) u = bp[t - o];
        __syncthreads();
        if (t < 128) bp[t] += u;
        __syncthreads();
    }
    int off = (blockIdx.x == 0) ? 0 : bp[blockIdx.x - 1];   // exclusive block offset

    int i = blockIdx.x * 1024 + t;
    int v = (i < N2) ? deg[i] : 0;
    sm[t] = v;
    __syncthreads();
#pragma unroll
    for (int o = 1; o < 1024; o <<= 1) {
        int u = (t >= o) ? sm[t - o] : 0;
        __syncthreads();
        sm[t] += u;
        __syncthreads();
    }
    int pos = off + sm[t] - v;   // exclusive
    if (i < N2) {
        rowptr[i] = pos;
        cur[i] = pos;
        if (i == N2 - 1) rowptr[N2] = pos + v;
    }
}

__global__ void k_fill(const int* __restrict__ ei, const float* __restrict__ attr,
                       int* __restrict__ cur, int* __restrict__ col, int E) {
    int e = (blockIdx.x * blockDim.x + threadIdx.x) * 2;
    if (e >= E) return;
    int2 s2 = *(const int2*)(ei + e);
    int2 d2 = *(const int2*)(ei + E + e);
    float4 a4 = *(const float4*)(attr + 2 * e);
    {
        int seg = 2 * d2.x + (a4.y > a4.x ? 1 : 0);
        col[atomicAdd(&cur[seg], 1)] = s2.x;
    }
    if (e + 1 < E) {
        int seg = 2 * d2.y + (a4.w > a4.z ? 1 : 0);
        col[atomicAdd(&cur[seg], 1)] = s2.y;
    }
}

// ---------------- tf32 MMA GEMM ----------------
__device__ __forceinline__ uint32_t f2tf(float f) {
    uint32_t u; asm("cvt.rna.tf32.f32 %0, %1;" : "=r"(u) : "f"(f)); return u;
}
__device__ __forceinline__ void mma_tf32(float* c, const uint32_t* a, uint32_t b0, uint32_t b1) {
    asm volatile("mma.sync.aligned.m16n8k8.row.col.f32.tf32.tf32.f32 "
        "{%0,%1,%2,%3}, {%4,%5,%6,%7}, {%8,%9}, {%0,%1,%2,%3};"
        : "+f"(c[0]), "+f"(c[1]), "+f"(c[2]), "+f"(c[3])
        : "r"(a[0]), "r"(a[1]), "r"(a[2]), "r"(a[3]), "r"(b0), "r"(b1));
}

#define AS_LD 36
#define BS_LD 100

__global__ __launch_bounds__(256) void k_gemm(
    const float* __restrict__ A, int M, int K,
    const float* __restrict__ B0, const float* __restrict__ B1, const float* __restrict__ B2,
    float* __restrict__ C, int ldc, const float* __restrict__ bias, int relu)
{
    __shared__ uint32_t As[128 * AS_LD];
    __shared__ uint32_t Bs[32 * BS_LD];
    const float* B = (blockIdx.y == 0) ? B0 : ((blockIdx.y == 1) ? B1 : B2);

    int tid = threadIdx.x;
    int lane = tid & 31;
    int warp = tid >> 5;
    int g = lane >> 2, tig = lane & 3;
    int mw = warp & 3;
    int nw = warp >> 2;
    int rowblock = blockIdx.x * 128;

    int ar[4], af[4], br_[3], bf_[3];
#pragma unroll
    for (int i = 0; i < 4; i++) { int id = tid + 256 * i; ar[i] = id >> 3; af[i] = id & 7; }
#pragma unroll
    for (int i = 0; i < 3; i++) { int id = tid + 256 * i; br_[i] = id / 24; bf_[i] = id % 24; }

    float c[2][6][4];
#pragma unroll
    for (int i = 0; i < 2; i++)
#pragma unroll
        for (int j = 0; j < 6; j++)
#pragma unroll
            for (int q = 0; q < 4; q++) c[i][j][q] = 0.f;

    const float4 z4 = make_float4(0.f, 0.f, 0.f, 0.f);
    float4 a_reg[4], b_reg[3];

#pragma unroll
    for (int i = 0; i < 4; i++) {
        int gr = rowblock + ar[i];
        a_reg[i] = (gr < M) ? __ldg((const float4*)(A + (size_t)gr * K) + af[i]) : z4;
    }
#pragma unroll
    for (int i = 0; i < 3; i++)
        b_reg[i] = __ldg((const float4*)(B + (size_t)br_[i] * 96) + bf_[i]);
#pragma unroll
    for (int i = 0; i < 4; i++) {
        uint4 u = make_uint4(f2tf(a_reg[i].x), f2tf(a_reg[i].y), f2tf(a_reg[i].z), f2tf(a_reg[i].w));
        *(uint4*)(&As[ar[i] * AS_LD + af[i] * 4]) = u;
    }
#pragma unroll
    for (int i = 0; i < 3; i++) {
        uint4 u = make_uint4(f2tf(b_reg[i].x), f2tf(b_reg[i].y), f2tf(b_reg[i].z), f2tf(b_reg[i].w));
        *(uint4*)(&Bs[br_[i] * BS_LD + bf_[i] * 4]) = u;
    }
    __syncthreads();

    for (int kb = 0; kb < K; kb += 32) {
        bool more = (kb + 32 < K);
        if (more) {
#pragma unroll
            for (int i = 0; i < 4; i++) {
                int gr = rowblock + ar[i];
                a_reg[i] = (gr < M) ? __ldg((const float4*)(A + (size_t)gr * K + kb + 32) + af[i]) : z4;
            }
#pragma unroll
            for (int i = 0; i < 3; i++)
                b_reg[i] = __ldg((const float4*)(B + (size_t)(kb + 32 + br_[i]) * 96) + bf_[i]);
        }
#pragma unroll
        for (int k8 = 0; k8 < 32; k8 += 8) {
            uint32_t a[2][4];
#pragma unroll
            for (int mt = 0; mt < 2; mt++) {
                int rb = mw * 32 + mt * 16;
                a[mt][0] = As[(rb + g) * AS_LD + k8 + tig];
                a[mt][1] = As[(rb + g + 8) * AS_LD + k8 + tig];
                a[mt][2] = As[(rb + g) * AS_LD + k8 + tig + 4];
                a[mt][3] = As[(rb + g + 8) * AS_LD + k8 + tig + 4];
            }
#pragma unroll
            for (int nt = 0; nt < 6; nt++) {
                int cb = nw * 48 + nt * 8;
                uint32_t b0 = Bs[(k8 + tig) * BS_LD + cb + g];
                uint32_t b1 = Bs[(k8 + tig + 4) * BS_LD + cb + g];
                mma_tf32(c[0][nt], a[0], b0, b1);
                mma_tf32(c[1][nt], a[1], b0, b1);
            }
        }
        __syncthreads();
        if (more) {
#pragma unroll
            for (int i = 0; i < 4; i++) {
                uint4 u = make_uint4(f2tf(a_reg[i].x), f2tf(a_reg[i].y), f2tf(a_reg[i].z), f2tf(a_reg[i].w));
                *(uint4*)(&As[ar[i] * AS_LD + af[i] * 4]) = u;
            }
#pragma unroll
            for (int i = 0; i < 3; i++) {
                uint4 u = make_uint4(f2tf(b_reg[i].x), f2tf(b_reg[i].y), f2tf(b_reg[i].z), f2tf(b_reg[i].w));
                *(uint4*)(&Bs[br_[i] * BS_LD + bf_[i] * 4]) = u;
            }
            __syncthreads();
        }
    }

    int colchunk = blockIdx.y * 96;
#pragma unroll
    for (int mt = 0; mt < 2; mt++) {
        int r0 = rowblock + mw * 32 + mt * 16 + g;
        int r1 = r0 + 8;
#pragma unroll
        for (int nt = 0; nt < 6; nt++) {
            int col = nw * 48 + nt * 8 + 2 * tig;
            float bx = 0.f, by = 0.f;
            if (bias) { bx = __ldg(bias + col); by = __ldg(bias + col + 1); }
            float v0 = c[mt][nt][0] + bx, v1 = c[mt][nt][1] + by;
            float v2 = c[mt][nt][2] + bx, v3 = c[mt][nt][3] + by;
            if (relu) {
                v0 = fmaxf(v0, 0.f); v1 = fmaxf(v1, 0.f);
                v2 = fmaxf(v2, 0.f); v3 = fmaxf(v3, 0.f);
            }
            if (r0 < M) *(float2*)(C + (size_t)r0 * ldc + colchunk + col) = make_float2(v0, v1);
            if (r1 < M) *(float2*)(C + (size_t)r1 * ldc + colchunk + col) = make_float2(v2, v3);
        }
    }
}

// ---------------- fused gather: clamped 4-wide, software-pipelined ----------------
// lanes 0..23 own one 16B chunk of the 384B message; single loop over both relations
__global__ void k_aggout(const float* __restrict__ T, const int* __restrict__ rowptr,
                         const int* __restrict__ col, const float* __restrict__ bias,
                         float* __restrict__ out, int N) {
    int warpi = (blockIdx.x * blockDim.x + threadIdx.x) >> 5;
    int lane = threadIdx.x & 31;
    if (warpi >= N) return;
    int n = warpi;
    int e00 = __ldg(&rowptr[2 * n]);
    int e01 = __ldg(&rowptr[2 * n + 1]);
    int e11 = __ldg(&rowptr[2 * n + 2]);
    int cl = (lane < 24) ? lane : 23;   // clamped chunk index

    float4 x = make_float4(0.f, 0.f, 0.f, 0.f);
    float4 y = make_float4(0.f, 0.f, 0.f, 0.f);

    if (e00 < e11) {
        int last = e11 - 1;
        float4 v[4];
        int m[4];                       // 0 invalid, 1 rel0, 2 rel1
#pragma unroll
        for (int q = 0; q < 4; q++) {
            int i = e00 + q;
            m[q] = (i < e11) ? ((i < e01) ? 1 : 2) : 0;
            int j = (i < last) ? i : last;
            int off = (j < e01) ? 96 : 192;
            v[q] = __ldg((const float4*)(T + (size_t)__ldg(&col[j]) * 288 + off) + cl);
        }
        for (int base = e00 + 4; base < e11; base += 4) {
            float4 w[4];
            int p[4];
#pragma unroll
            for (int q = 0; q < 4; q++) {
                int i = base + q;
                p[q] = (i < e11) ? ((i < e01) ? 1 : 2) : 0;
                int j = (i < last) ? i : last;
                int off = (j < e01) ? 96 : 192;
                w[q] = __ldg((const float4*)(T + (size_t)__ldg(&col[j]) * 288 + off) + cl);
            }
#pragma unroll
            for (int q = 0; q < 4; q++) {
                if (m[q] == 1)      { x.x += v[q].x; x.y += v[q].y; x.z += v[q].z; x.w += v[q].w; }
                else if (m[q] == 2) { y.x += v[q].x; y.y += v[q].y; y.z += v[q].z; y.w += v[q].w; }
                v[q] = w[q]; m[q] = p[q];
            }
        }
#pragma unroll
        for (int q = 0; q < 4; q++) {
            if (m[q] == 1)      { x.x += v[q].x; x.y += v[q].y; x.z += v[q].z; x.w += v[q].w; }
            else if (m[q] == 2) { y.x += v[q].x; y.y += v[q].y; y.z += v[q].z; y.w += v[q].w; }
        }
    }

    if (lane < 24) {
        float i0 = 1.f / fmaxf((float)(e01 - e00), 1.f);
        float i1 = 1.f / fmaxf((float)(e11 - e01), 1.f);
        float4 r = __ldg((const float4*)(T + (size_t)n * 288) + lane);
        float4 b = __ldg((const float4*)bias + lane);
        float4 o;
        o.x = fmaxf(b.x + r.x + x.x * i0 + y.x * i1, 0.f);
        o.y = fmaxf(b.y + r.y + x.y * i0 + y.y * i1, 0.f);
        o.z = fmaxf(b.z + r.z + x.z * i0 + y.z * i1, 0.f);
        o.w = fmaxf(b.w + r.w + x.w * i0 + y.w * i1, 0.f);
        *((float4*)(out + (size_t)n * DD) + lane) = o;
    }
}

// ---------------- launch ----------------
extern "C" void kernel_launch(void* const* d_in, const int* in_sizes, int n_in,
                              void* d_out, int out_size) {
    const float* x    = (const float*)d_in[0];
    const int*   ei   = (const int*)d_in[1];
    const float* attr = (const float*)d_in[2];
    const float* Wf   = (const float*)d_in[3];
    const float* bf   = (const float*)d_in[4];
    const float* W    = (const float*)d_in[5];
    const float* root = (const float*)d_in[6];
    const float* bias = (const float*)d_in[7];
    float* out = (float*)d_out;

    int E = in_sizes[1] / 2;
    int N = in_sizes[0] / FF;
    int N2 = 2 * N;
    int nb = (N2 + 1023) / 1024;

    void *pA, *pB, *pT, *pWfT, *pdg, *prp, *pc, *pcol, *pbp;
    cudaGetSymbolAddress(&pA, g_hA);
    cudaGetSymbolAddress(&pB, g_hB);
    cudaGetSymbolAddress(&pT, g_T);
    cudaGetSymbolAddress(&pWfT, g_WfT);
    cudaGetSymbolAddress(&pdg, g_deg);
    cudaGetSymbolAddress(&prp, g_rowptr);
    cudaGetSymbolAddress(&pc, g_cur);
    cudaGetSymbolAddress(&pcol, g_col);
    cudaGetSymbolAddress(&pbp, g_bpart);

    k_prep<<<(N2 + 255) / 256, 256>>>(Wf, (float*)pWfT, (int*)pdg, N2);
    k_hist<<<(E / 2 + 255) / 256, 256>>>(ei, attr, (int*)pdg, E);
    k_scanA<<<nb, 1024>>>((int*)pdg, (int*)pbp, N2);
    k_scanC<<<nb, 1024>>>((int*)pdg, (int*)pbp, (int*)prp, (int*)pc, N2, nb);
    k_fill<<<(E / 2 + 255) / 256, 256>>>(ei, attr, (int*)pc, (int*)pcol, E);

    int mblocks = (N + 127) / 128;
    // h = relu(x @ WfT + bf)
    k_gemm<<<dim3(mblocks, 1), 256>>>(x, N, FF, (const float*)pWfT, nullptr, nullptr,
                                      (float*)pA, DD, bf, 1);

    const float* W0 = W;
    const float* W1 = W + DD * DD;
    float* hin = (float*)pA;
    float* hout = (float*)pB;
    for (int it = 0; it < 3; it++) {
        // T = [h@root | h@W0 | h@W1]
        k_gemm<<<dim3(mblocks, 3), 256>>>(hin, N, DD, root, W0, W1,
                                          (float*)pT, 3 * DD, nullptr, 0);
        float* o = (it == 2) ? out : hout;
        k_aggout<<<(N * 32 + 255) / 256, 256>>>((const float*)pT, (int*)prp, (int*)pcol,
                                                bias, o, N);
        float* t = hin; hin = hout; hout = t;
    }
}

// round 11
// speedup vs baseline: 1.0970x; 1.0970x over previous
#include <cuda_runtime.h>
#include <cstdint>

#define NN 50000
#define EE 800000
#define DD 96
#define FF 128

// ---------------- scratch ----------------
__device__ __align__(16) float g_hA[NN * DD];
__device__ __align__(16) float g_hB[NN * DD];
__device__ __align__(16) float g_T[NN * 3 * DD];   // [N][288]: root | rel0 | rel1
__device__ __align__(16) float g_WfT[FF * DD];
__device__ int g_deg[2 * NN];
__device__ int g_cur[2 * NN];
__device__ int g_rowptr[2 * NN + 1];
__device__ int g_col[EE];
__device__ int g_bpart[256];

// ---------------- prep: zero deg + transpose Wf ----------------
__global__ void k_prep(const float* __restrict__ Wf, float* __restrict__ WfT,
                       int* __restrict__ deg, int N2) {
    int i = blockIdx.x * blockDim.x + threadIdx.x;
    if (i < N2) deg[i] = 0;
    if (i < DD * FF) {
        int d = i >> 7, k = i & 127;
        WfT[k * DD + d] = Wf[i];
    }
}

// ---------------- CSR build ----------------
__global__ void k_hist(const int* __restrict__ ei, const float* __restrict__ attr,
                       int* __restrict__ deg, int E) {
    int e = (blockIdx.x * blockDim.x + threadIdx.x) * 2;
    if (e >= E) return;
    int2 d2 = *(const int2*)(ei + E + e);
    float4 a4 = *(const float4*)(attr + 2 * e);
    atomicAdd(&deg[2 * d2.x + (a4.y > a4.x ? 1 : 0)], 1);
    if (e + 1 < E)
        atomicAdd(&deg[2 * d2.y + (a4.w > a4.z ? 1 : 0)], 1);
}

// --- A) block partial sums ---
__global__ __launch_bounds__(1024) void k_scanA(const int* __restrict__ deg,
                                                int* __restrict__ bpart, int N2) {
    __shared__ int red[32];
    int t = threadIdx.x;
    int i = blockIdx.x * 1024 + t;
    int v = (i < N2) ? deg[i] : 0;
#pragma unroll
    for (int o = 16; o; o >>= 1) v += __shfl_down_sync(~0u, v, o);
    if ((t & 31) == 0) red[t >> 5] = v;
    __syncthreads();
    if (t < 32) {
        int s = red[t];
#pragma unroll
        for (int o = 16; o; o >>= 1) s += __shfl_down_sync(~0u, s, o);
        if (t == 0) bpart[blockIdx.x] = s;
    }
}

// --- C) in-block scan of partials + per-block exclusive scan + offset ---
__global__ __launch_bounds__(1024) void k_scanC(const int* __restrict__ deg,
                                                const int* __restrict__ bpart,
                                                int* __restrict__ rowptr,
                                                int* __restrict__ cur, int N2, int nb) {
    __shared__ int sm[1024];
    __shared__ int bp[128];
    int t = threadIdx.x;
    if (t < 128) bp[t] = (t < nb) ? __ldg(&bpart[t]) : 0;
    __syncthreads();
#pragma unroll
    for (int o = 1; o < 128; o <<= 1) {
        int u = 0;
        if (t < 128 && t >= o) u = bp[t - o];
        __syncthreads();
        if (t < 128) bp[t] += u;
        __syncthreads();
    }
    int off = (blockIdx.x == 0) ? 0 : bp[blockIdx.x - 1];   // exclusive block offset

    int i = blockIdx.x * 1024 + t;
    int v = (i < N2) ? deg[i] : 0;
    sm[t] = v;
    __syncthreads();
#pragma unroll
    for (int o = 1; o < 1024; o <<= 1) {
        int u = (t >= o) ? sm[t - o] : 0;
        __syncthreads();
        sm[t] += u;
        __syncthreads();
    }
    int pos = off + sm[t] - v;   // exclusive
    if (i < N2) {
        rowptr[i] = pos;
        cur[i] = pos;
        if (i == N2 - 1) rowptr[N2] = pos + v;
    }
}

__global__ void k_fill(const int* __restrict__ ei, const float* __restrict__ attr,
                       int* __restrict__ cur, int* __restrict__ col, int E) {
    int e = (blockIdx.x * blockDim.x + threadIdx.x) * 2;
    if (e >= E) return;
    int2 s2 = *(const int2*)(ei + e);
    int2 d2 = *(const int2*)(ei + E + e);
    float4 a4 = *(const float4*)(attr + 2 * e);
    {
        int seg = 2 * d2.x + (a4.y > a4.x ? 1 : 0);
        col[atomicAdd(&cur[seg], 1)] = s2.x;
    }
    if (e + 1 < E) {
        int seg = 2 * d2.y + (a4.w > a4.z ? 1 : 0);
        col[atomicAdd(&cur[seg], 1)] = s2.y;
    }
}

// ---------------- tf32 MMA GEMM ----------------
__device__ __forceinline__ uint32_t f2tf(float f) {
    uint32_t u; asm("cvt.rna.tf32.f32 %0, %1;" : "=r"(u) : "f"(f)); return u;
}
__device__ __forceinline__ void mma_tf32(float* c, const uint32_t* a, uint32_t b0, uint32_t b1) {
    asm volatile("mma.sync.aligned.m16n8k8.row.col.f32.tf32.tf32.f32 "
        "{%0,%1,%2,%3}, {%4,%5,%6,%7}, {%8,%9}, {%0,%1,%2,%3};"
        : "+f"(c[0]), "+f"(c[1]), "+f"(c[2]), "+f"(c[3])
        : "r"(a[0]), "r"(a[1]), "r"(a[2]), "r"(a[3]), "r"(b0), "r"(b1));
}

#define AS_LD 36
#define BS_LD 100

__global__ __launch_bounds__(256) void k_gemm(
    const float* __restrict__ A, int M, int K,
    const float* __restrict__ B0, const float* __restrict__ B1, const float* __restrict__ B2,
    float* __restrict__ C, int ldc, const float* __restrict__ bias, int relu)
{
    __shared__ uint32_t As[128 * AS_LD];
    __shared__ uint32_t Bs[32 * BS_LD];
    const float* B = (blockIdx.y == 0) ? B0 : ((blockIdx.y == 1) ? B1 : B2);

    int tid = threadIdx.x;
    int lane = tid & 31;
    int warp = tid >> 5;
    int g = lane >> 2, tig = lane & 3;
    int mw = warp & 3;
    int nw = warp >> 2;
    int rowblock = blockIdx.x * 128;

    int ar[4], af[4], br_[3], bf_[3];
#pragma unroll
    for (int i = 0; i < 4; i++) { int id = tid + 256 * i; ar[i] = id >> 3; af[i] = id & 7; }
#pragma unroll
    for (int i = 0; i < 3; i++) { int id = tid + 256 * i; br_[i] = id / 24; bf_[i] = id % 24; }

    float c[2][6][4];
#pragma unroll
    for (int i = 0; i < 2; i++)
#pragma unroll
        for (int j = 0; j < 6; j++)
#pragma unroll
            for (int q = 0; q < 4; q++) c[i][j][q] = 0.f;

    const float4 z4 = make_float4(0.f, 0.f, 0.f, 0.f);
    float4 a_reg[4], b_reg[3];

#pragma unroll
    for (int i = 0; i < 4; i++) {
        int gr = rowblock + ar[i];
        a_reg[i] = (gr < M) ? __ldg((const float4*)(A + (size_t)gr * K) + af[i]) : z4;
    }
#pragma unroll
    for (int i = 0; i < 3; i++)
        b_reg[i] = __ldg((const float4*)(B + (size_t)br_[i] * 96) + bf_[i]);
#pragma unroll
    for (int i = 0; i < 4; i++) {
        uint4 u = make_uint4(f2tf(a_reg[i].x), f2tf(a_reg[i].y), f2tf(a_reg[i].z), f2tf(a_reg[i].w));
        *(uint4*)(&As[ar[i] * AS_LD + af[i] * 4]) = u;
    }
#pragma unroll
    for (int i = 0; i < 3; i++) {
        uint4 u = make_uint4(f2tf(b_reg[i].x), f2tf(b_reg[i].y), f2tf(b_reg[i].z), f2tf(b_reg[i].w));
        *(uint4*)(&Bs[br_[i] * BS_LD + bf_[i] * 4]) = u;
    }
    __syncthreads();

    for (int kb = 0; kb < K; kb += 32) {
        bool more = (kb + 32 < K);
        if (more) {
#pragma unroll
            for (int i = 0; i < 4; i++) {
                int gr = rowblock + ar[i];
                a_reg[i] = (gr < M) ? __ldg((const float4*)(A + (size_t)gr * K + kb + 32) + af[i]) : z4;
            }
#pragma unroll
            for (int i = 0; i < 3; i++)
                b_reg[i] = __ldg((const float4*)(B + (size_t)(kb + 32 + br_[i]) * 96) + bf_[i]);
        }
#pragma unroll
        for (int k8 = 0; k8 < 32; k8 += 8) {
            uint32_t a[2][4];
#pragma unroll
            for (int mt = 0; mt < 2; mt++) {
                int rb = mw * 32 + mt * 16;
                a[mt][0] = As[(rb + g) * AS_LD + k8 + tig];
                a[mt][1] = As[(rb + g + 8) * AS_LD + k8 + tig];
                a[mt][2] = As[(rb + g) * AS_LD + k8 + tig + 4];
                a[mt][3] = As[(rb + g + 8) * AS_LD + k8 + tig + 4];
            }
#pragma unroll
            for (int nt = 0; nt < 6; nt++) {
                int cb = nw * 48 + nt * 8;
                uint32_t b0 = Bs[(k8 + tig) * BS_LD + cb + g];
                uint32_t b1 = Bs[(k8 + tig + 4) * BS_LD + cb + g];
                mma_tf32(c[0][nt], a[0], b0, b1);
                mma_tf32(c[1][nt], a[1], b0, b1);
            }
        }
        __syncthreads();
        if (more) {
#pragma unroll
            for (int i = 0; i < 4; i++) {
                uint4 u = make_uint4(f2tf(a_reg[i].x), f2tf(a_reg[i].y), f2tf(a_reg[i].z), f2tf(a_reg[i].w));
                *(uint4*)(&As[ar[i] * AS_LD + af[i] * 4]) = u;
            }
#pragma unroll
            for (int i = 0; i < 3; i++) {
                uint4 u = make_uint4(f2tf(b_reg[i].x), f2tf(b_reg[i].y), f2tf(b_reg[i].z), f2tf(b_reg[i].w));
                *(uint4*)(&Bs[br_[i] * BS_LD + bf_[i] * 4]) = u;
            }
            __syncthreads();
        }
    }

    int colchunk = blockIdx.y * 96;
#pragma unroll
    for (int mt = 0; mt < 2; mt++) {
        int r0 = rowblock + mw * 32 + mt * 16 + g;
        int r1 = r0 + 8;
#pragma unroll
        for (int nt = 0; nt < 6; nt++) {
            int col = nw * 48 + nt * 8 + 2 * tig;
            float bx = 0.f, by = 0.f;
            if (bias) { bx = __ldg(bias + col); by = __ldg(bias + col + 1); }
            float v0 = c[mt][nt][0] + bx, v1 = c[mt][nt][1] + by;
            float v2 = c[mt][nt][2] + bx, v3 = c[mt][nt][3] + by;
            if (relu) {
                v0 = fmaxf(v0, 0.f); v1 = fmaxf(v1, 0.f);
                v2 = fmaxf(v2, 0.f); v3 = fmaxf(v3, 0.f);
            }
            if (r0 < M) *(float2*)(C + (size_t)r0 * ldc + colchunk + col) = make_float2(v0, v1);
            if (r1 < M) *(float2*)(C + (size_t)r1 * ldc + colchunk + col) = make_float2(v2, v3);
        }
    }
}

// ---------------- fused float4 gather + mean + root + bias + relu ----------------
// lanes 0..23 each own one 16B chunk of the 384B message; 1 LDG.128 per edge
__global__ void k_aggout(const float* __restrict__ T, const int* __restrict__ rowptr,
                         const int* __restrict__ col, const float* __restrict__ bias,
                         float* __restrict__ out, int N) {
    int warpi = (blockIdx.x * blockDim.x + threadIdx.x) >> 5;
    int lane = threadIdx.x & 31;
    if (warpi >= N) return;
    int n = warpi;
    int e00 = __ldg(&rowptr[2 * n]);
    int e01 = __ldg(&rowptr[2 * n + 1]);
    int e11 = __ldg(&rowptr[2 * n + 2]);
    int cl = (lane < 24) ? lane : 23;   // clamped chunk index (dup addr, HW dedups)

    float4 x = make_float4(0.f, 0.f, 0.f, 0.f);
    float4 y = make_float4(0.f, 0.f, 0.f, 0.f);

    int e = e00;
    for (; e + 3 < e01; e += 4) {
        const float4* p0 = (const float4*)(T + (size_t)__ldg(&col[e])     * 288 + 96);
        const float4* p1 = (const float4*)(T + (size_t)__ldg(&col[e + 1]) * 288 + 96);
        const float4* p2 = (const float4*)(T + (size_t)__ldg(&col[e + 2]) * 288 + 96);
        const float4* p3 = (const float4*)(T + (size_t)__ldg(&col[e + 3]) * 288 + 96);
        float4 v0 = __ldg(p0 + cl), v1 = __ldg(p1 + cl), v2 = __ldg(p2 + cl), v3 = __ldg(p3 + cl);
        x.x += (v0.x + v1.x) + (v2.x + v3.x);
        x.y += (v0.y + v1.y) + (v2.y + v3.y);
        x.z += (v0.z + v1.z) + (v2.z + v3.z);
        x.w += (v0.w + v1.w) + (v2.w + v3.w);
    }
    for (; e < e01; e++) {
        const float4* p = (const float4*)(T + (size_t)__ldg(&col[e]) * 288 + 96);
        float4 v = __ldg(p + cl);
        x.x += v.x; x.y += v.y; x.z += v.z; x.w += v.w;
    }
    e = e01;
    for (; e + 3 < e11; e += 4) {
        const float4* p0 = (const float4*)(T + (size_t)__ldg(&col[e])     * 288 + 192);
        const float4* p1 = (const float4*)(T + (size_t)__ldg(&col[e + 1]) * 288 + 192);
        const float4* p2 = (const float4*)(T + (size_t)__ldg(&col[e + 2]) * 288 + 192);
        const float4* p3 = (const float4*)(T + (size_t)__ldg(&col[e + 3]) * 288 + 192);
        float4 v0 = __ldg(p0 + cl), v1 = __ldg(p1 + cl), v2 = __ldg(p2 + cl), v3 = __ldg(p3 + cl);
        y.x += (v0.x + v1.x) + (v2.x + v3.x);
        y.y += (v0.y + v1.y) + (v2.y + v3.y);
        y.z += (v0.z + v1.z) + (v2.z + v3.z);
        y.w += (v0.w + v1.w) + (v2.w + v3.w);
    }
    for (; e < e11; e++) {
        const float4* p = (const float4*)(T + (size_t)__ldg(&col[e]) * 288 + 192);
        float4 v = __ldg(p + cl);
        y.x += v.x; y.y += v.y; y.z += v.z; y.w += v.w;
    }

    if (lane < 24) {
        float i0 = 1.f / fmaxf((float)(e01 - e00), 1.f);
        float i1 = 1.f / fmaxf((float)(e11 - e01), 1.f);
        float4 r = __ldg((const float4*)(T + (size_t)n * 288) + lane);
        float4 b = __ldg((const float4*)bias + lane);
        float4 o;
        o.x = fmaxf(b.x + r.x + x.x * i0 + y.x * i1, 0.f);
        o.y = fmaxf(b.y + r.y + x.y * i0 + y.y * i1, 0.f);
        o.z = fmaxf(b.z + r.z + x.z * i0 + y.z * i1, 0.f);
        o.w = fmaxf(b.w + r.w + x.w * i0 + y.w * i1, 0.f);
        *((float4*)(out + (size_t)n * DD) + lane) = o;
    }
}

// ---------------- launch ----------------
extern "C" void kernel_launch(void* const* d_in, const int* in_sizes, int n_in,
                              void* d_out, int out_size) {
    const float* x    = (const float*)d_in[0];
    const int*   ei   = (const int*)d_in[1];
    const float* attr = (const float*)d_in[2];
    const float* Wf   = (const float*)d_in[3];
    const float* bf   = (const float*)d_in[4];
    const float* W    = (const float*)d_in[5];
    const float* root = (const float*)d_in[6];
    const float* bias = (const float*)d_in[7];
    float* out = (float*)d_out;

    int E = in_sizes[1] / 2;
    int N = in_sizes[0] / FF;
    int N2 = 2 * N;
    int nb = (N2 + 1023) / 1024;

    void *pA, *pB, *pT, *pWfT, *pdg, *prp, *pc, *pcol, *pbp;
    cudaGetSymbolAddress(&pA, g_hA);
    cudaGetSymbolAddress(&pB, g_hB);
    cudaGetSymbolAddress(&pT, g_T);
    cudaGetSymbolAddress(&pWfT, g_WfT);
    cudaGetSymbolAddress(&pdg, g_deg);
    cudaGetSymbolAddress(&prp, g_rowptr);
    cudaGetSymbolAddress(&pc, g_cur);
    cudaGetSymbolAddress(&pcol, g_col);
    cudaGetSymbolAddress(&pbp, g_bpart);

    int mblocks = (N + 127) / 128;

    // launch order arranged so the GEMM (k_lin use) is the 4th launch —
    // ncu empirically profiles launch #4, giving us the first GEMM profile.
    k_prep<<<(N2 + 255) / 256, 256>>>(Wf, (float*)pWfT, (int*)pdg, N2);       // 1
    k_hist<<<(E / 2 + 255) / 256, 256>>>(ei, attr, (int*)pdg, E);             // 2
    k_scanA<<<nb, 1024>>>((int*)pdg, (int*)pbp, N2);                          // 3
    // h = relu(x @ WfT + bf)  (independent of scan/fill; only needs prep)
    k_gemm<<<dim3(mblocks, 1), 256>>>(x, N, FF, (const float*)pWfT, nullptr, nullptr,
                                      (float*)pA, DD, bf, 1);                 // 4 <- profiled
    k_scanC<<<nb, 1024>>>((int*)pdg, (int*)pbp, (int*)prp, (int*)pc, N2, nb); // 5
    k_fill<<<(E / 2 + 255) / 256, 256>>>(ei, attr, (int*)pc, (int*)pcol, E);  // 6

    const float* W0 = W;
    const float* W1 = W + DD * DD;
    float* hin = (float*)pA;
    float* hout = (float*)pB;
    for (int it = 0; it < 3; it++) {
        // T = [h@root | h@W0 | h@W1]
        k_gemm<<<dim3(mblocks, 3), 256>>>(hin, N, DD, root, W0, W1,
                                          (float*)pT, 3 * DD, nullptr, 0);
        float* o = (it == 2) ? out : hout;
        k_aggout<<<(N * 32 + 255) / 256, 256>>>((const float*)pT, (int*)prp, (int*)pcol,
                                                bias, o, N);
        float* t = hin; hin = hout; hout = t;
    }
}